// round 5
// baseline (speedup 1.0000x reference)
#include <cuda_runtime.h>

#define BATCH 262144
#define DIM   128
#define K     10

#define NBLK1 2048
#define T1    256                       // 8 warps
#define ROWS_PER_BLK (BATCH / NBLK1)    // 128
#define ITERS (ROWS_PER_BLK / 64)       // 2  (8 warps x 8 rows per iter)

#define NBLK2 1024
#define T2    256
#define RPB2  (BATCH / NBLK2)           // 256 rows per k_p block

// Scratch (graph-capturable, no allocs). g_part fully overwritten each replay;
// g_ctr returns to 0 at the end of every k_q (last block resets it).
__device__ float g_part[NBLK1][K];
__device__ float g_invf[K];
__device__ int   g_ctr = 0;

typedef unsigned long long u64;

__device__ __forceinline__ u64 pack2(float lo, float hi) {
    u64 r; asm("mov.b64 %0, {%1, %2};" : "=l"(r) : "f"(lo), "f"(hi)); return r;
}
__device__ __forceinline__ void unpack2(u64 v, float& lo, float& hi) {
    asm("mov.b64 {%0, %1}, %2;" : "=f"(lo), "=f"(hi) : "l"(v));
}
__device__ __forceinline__ void fma2(u64& acc, u64 a, u64 b) {
    asm("fma.rn.f32x2 %0, %1, %2, %0;" : "+l"(acc) : "l"(a), "l"(b));
}

// Kernel 1: q = rownorm( 1/(1 + ||z - mu||^2) ) + column sums -> g_invf.
// Warp layout: 8 rows x 4 lanes (r = lane>>2, c = lane&3). Lane holds 32 dims
// of its row in registers (8 front-batched LDG.128, coalesced 8-line pattern).
// Dot reduction = 2 shfl.xor levels. Epilogue on c==0 lanes only.
__global__ __launch_bounds__(T1) void k_q(
    const float* __restrict__ z,
    const float* __restrict__ c,
    float* __restrict__ qout)
{
    __shared__ float4 s_c[K][DIM / 4];   // 5120 B
    __shared__ float  s_cn[K];
    __shared__ float  s_part[8][K];
    __shared__ int    s_last;

    const int tid  = threadIdx.x;
    const int lane = tid & 31;
    const int wrp  = tid >> 5;
    const int r    = lane >> 2;          // row within warp group (0..7)
    const int cc4  = lane & 3;           // dim-quarter (0..3)

    for (int i = tid; i < K * DIM / 4; i += T1)
        ((float4*)s_c)[i] = ((const float4*)c)[i];
    __syncthreads();
    if (tid < K) {
        float s = 0.0f;
        #pragma unroll
        for (int d = 0; d < DIM / 4; d++) {
            float4 v = s_c[tid][d];
            s = fmaf(v.x, v.x, fmaf(v.y, v.y, fmaf(v.z, v.z, fmaf(v.w, v.w, s))));
        }
        s_cn[tid] = s;
    }
    __syncthreads();

    float csum[K];
    #pragma unroll
    for (int j = 0; j < K; j++) csum[j] = 0.0f;

    #pragma unroll
    for (int t = 0; t < ITERS; t++) {
        const int row = blockIdx.x * ROWS_PER_BLK + t * 64 + wrp * 8 + r;
        const float4* zrow = (const float4*)(z + (size_t)row * DIM);

        // Front-batched, coalesced: for fixed s, warp covers 8 rows x 64B.
        float4 zv[8];
        #pragma unroll
        for (int s = 0; s < 8; s++) zv[s] = zrow[s * 4 + cc4];

        u64 dot[K], zn = 0ull;
        #pragma unroll
        for (int j = 0; j < K; j++) dot[j] = 0ull;

        #pragma unroll
        for (int s = 0; s < 8; s++) {
            u64 a01 = pack2(zv[s].x, zv[s].y), a23 = pack2(zv[s].z, zv[s].w);
            fma2(zn, a01, a01); fma2(zn, a23, a23);
            #pragma unroll
            for (int j = 0; j < K; j++) {
                float4 cf = s_c[j][s * 4 + cc4];   // 4-addr, 8-way multicast
                u64 c01 = pack2(cf.x, cf.y), c23 = pack2(cf.z, cf.w);
                fma2(dot[j], a01, c01); fma2(dot[j], a23, c23);
            }
        }

        float lo, hi;
        unpack2(zn, lo, hi);
        float zz = lo + hi;
        zz += __shfl_xor_sync(0xFFFFFFFFu, zz, 1);
        zz += __shfl_xor_sync(0xFFFFFFFFu, zz, 2);

        float dsum[K];
        #pragma unroll
        for (int j = 0; j < K; j++) {
            unpack2(dot[j], lo, hi);
            float d = lo + hi;
            d += __shfl_xor_sync(0xFFFFFFFFu, d, 1);
            d += __shfl_xor_sync(0xFFFFFFFFu, d, 2);
            dsum[j] = d;
        }

        if (cc4 == 0) {                   // one lane per row does the epilogue
            const float zz1 = 1.0f + zz;
            float q[K], rsum = 0.0f;
            #pragma unroll
            for (int j = 0; j < K; j++) {
                float v = __fdividef(1.0f, fmaf(-2.0f, dsum[j], zz1 + s_cn[j]));
                q[j] = v; rsum += v;
            }
            const float inv = __fdividef(1.0f, rsum);
            float* orow = qout + (size_t)row * K;
            #pragma unroll
            for (int j = 0; j < K; j++) { q[j] *= inv; csum[j] += q[j]; }
            #pragma unroll
            for (int m = 0; m < 5; m++) {
                float2 v; v.x = q[2 * m]; v.y = q[2 * m + 1];
                *(float2*)(orow + 2 * m) = v;
            }
        }
    }

    // Block-level column-sum reduction (csum is 0 on non-c0 lanes).
    #pragma unroll
    for (int j = 0; j < K; j++) {
        float v = csum[j];
        #pragma unroll
        for (int m = 16; m > 0; m >>= 1) v += __shfl_xor_sync(0xFFFFFFFFu, v, m);
        if (lane == 0) s_part[wrp][j] = v;
    }
    __syncthreads();
    if (tid < K) {
        float s = 0.0f;
        #pragma unroll
        for (int w = 0; w < 8; w++) s += s_part[w][tid];
        g_part[blockIdx.x][tid] = s;
    }

    // Last block finalizes colsums -> g_invf (int atomic: deterministic).
    if (tid == 0) {
        __threadfence();
        s_last = (atomicAdd(&g_ctr, 1) == NBLK1 - 1);
    }
    __syncthreads();
    if (s_last) {
        __threadfence();
        float acc[K];
        #pragma unroll
        for (int j = 0; j < K; j++) acc[j] = 0.0f;
        for (int rr = tid; rr < NBLK1; rr += T1) {
            #pragma unroll
            for (int j = 0; j < K; j++) acc[j] += g_part[rr][j];
        }
        #pragma unroll
        for (int j = 0; j < K; j++) {
            float v = acc[j];
            #pragma unroll
            for (int m = 16; m > 0; m >>= 1) v += __shfl_xor_sync(0xFFFFFFFFu, v, m);
            if (lane == 0) s_part[wrp][j] = v;
        }
        __syncthreads();
        if (tid < K) {
            float s = 0.0f;
            #pragma unroll
            for (int w = 0; w < 8; w++) s += s_part[w][tid];
            g_invf[tid] = __fdividef(1.0f, s);
        }
        if (tid == 0) g_ctr = 0;    // reset for next replay
    }
}

// Kernel 2: p = rownorm( q^2 * g_invf ). Fully coalesced IO via smem staging.
__global__ __launch_bounds__(T2) void k_p(
    const float* __restrict__ q,
    float* __restrict__ p)
{
    __shared__ float s_q[RPB2 * K];   // 10240 B
    __shared__ float s_p[RPB2 * K];   // 10240 B
    __shared__ float s_inv[K];

    const int tid = threadIdx.x;
    if (tid < K) s_inv[tid] = g_invf[tid];

    const float4* qg = (const float4*)(q + (size_t)blockIdx.x * RPB2 * K);
    #pragma unroll
    for (int i = 0; i < (RPB2 * K / 4 + T2 - 1) / T2; i++) {
        const int idx = i * T2 + tid;
        if (idx < RPB2 * K / 4) ((float4*)s_q)[idx] = qg[idx];
    }
    __syncthreads();

    float w[K], s = 0.0f;
    const float* qr = s_q + tid * K;
    #pragma unroll
    for (int j = 0; j < K; j++) {
        float v = qr[j];
        w[j] = v * v * s_inv[j];
        s += w[j];
    }
    const float inv = __fdividef(1.0f, s);
    float* pr = s_p + tid * K;
    #pragma unroll
    for (int j = 0; j < K; j++) pr[j] = w[j] * inv;
    __syncthreads();

    float4* pg = (float4*)(p + (size_t)blockIdx.x * RPB2 * K);
    #pragma unroll
    for (int i = 0; i < (RPB2 * K / 4 + T2 - 1) / T2; i++) {
        const int idx = i * T2 + tid;
        if (idx < RPB2 * K / 4) pg[idx] = ((const float4*)s_p)[idx];
    }
}

extern "C" void kernel_launch(void* const* d_in, const int* in_sizes, int n_in,
                              void* d_out, int out_size) {
    const float* z = (const float*)d_in[0];
    const float* c = (const float*)d_in[1];
    float* qout = (float*)d_out;
    float* pout = (float*)d_out + (size_t)BATCH * K;

    k_q<<<NBLK1, T1>>>(z, c, qout);
    k_p<<<NBLK2, T2>>>(qout, pout);
}

// round 7
// speedup vs baseline: 12.9590x; 12.9590x over previous
#include <cuda_runtime.h>

#define BATCH 262144
#define DIM   128
#define K     10

#define T1        128
#define TILE_ROWS 128
#define NTILES    (BATCH / TILE_ROWS)    // 2048
#define NBLK1     444                    // 148 SMs x 3 resident blocks

#define NBLK2 1024
#define T2    256
#define RPB2  (BATCH / NBLK2)            // 256

// Cluster centers in constant memory (uniform access -> LDCU, off the LSU).
__constant__ float4 c_cent[K][DIM / 4];

// Scratch (no allocs). g_part overwritten every launch; g_ctr returns to 0.
__device__ float g_part[NBLK1][K];
__device__ float g_invf[K];
__device__ int   g_ctr = 0;

typedef unsigned long long u64;

__device__ __forceinline__ u64 pack2(float lo, float hi) {
    u64 r; asm("mov.b64 %0, {%1, %2};" : "=l"(r) : "f"(lo), "f"(hi)); return r;
}
__device__ __forceinline__ void unpack2(u64 v, float& lo, float& hi) {
    asm("mov.b64 {%0, %1}, %2;" : "=f"(lo), "=f"(hi) : "l"(v));
}
__device__ __forceinline__ void fma2(u64& acc, u64 a, u64 b) {
    asm("fma.rn.f32x2 %0, %1, %2, %0;" : "+l"(acc) : "l"(a), "l"(b));
}

// Kernel 1: q = rownorm( 1/(1 + ||z - mu||^2) ), colsums -> g_invf.
// Thread owns one row of each staged 128-row tile. z: coalesced LDG -> swizzled
// smem -> conflict-free LDS. Centers: constant memory (uniform, off the LSU).
__global__ __launch_bounds__(T1) void k_q(
    const float* __restrict__ z,
    float* __restrict__ qout)
{
    __shared__ float4 s_z[TILE_ROWS * 32];   // 64 KB swizzled tile
    __shared__ float  s_cn[K];
    __shared__ float  s_part[4][K];
    __shared__ int    s_last;

    const int tid  = threadIdx.x;
    const int lane = tid & 31;
    const int wrp  = tid >> 5;
    const int r7   = tid & 7;

    if (tid < K) {
        float s = 0.0f;
        #pragma unroll
        for (int d = 0; d < DIM / 4; d++) {
            float4 v = c_cent[tid][d];
            s = fmaf(v.x, v.x, fmaf(v.y, v.y, fmaf(v.z, v.z, fmaf(v.w, v.w, s))));
        }
        s_cn[tid] = s;    // first use is after the staging barrier
    }

    float csum[K];
    #pragma unroll
    for (int j = 0; j < K; j++) csum[j] = 0.0f;

    for (int tile = blockIdx.x; tile < NTILES; tile += NBLK1) {
        const float4* zg = (const float4*)z + (size_t)tile * TILE_ROWS * 32;

        // Stage: per k2, each warp loads 512B contiguous; swizzled STS.
        #pragma unroll
        for (int k2 = 0; k2 < 32; k2++) {
            const int g   = k2 * T1 + tid;     // [0, 4096)
            const int row = g >> 5;
            const int i   = g & 31;
            s_z[row * 32 + (i ^ (row & 7))] = zg[g];
        }
        __syncthreads();

        u64 dot[K], zn = 0ull;
        #pragma unroll
        for (int j = 0; j < K; j++) dot[j] = 0ull;

        #pragma unroll 8
        for (int i = 0; i < 32; i++) {
            float4 a = s_z[tid * 32 + (i ^ r7)];
            u64 a01 = pack2(a.x, a.y), a23 = pack2(a.z, a.w);
            fma2(zn, a01, a01); fma2(zn, a23, a23);
            #pragma unroll
            for (int j = 0; j < K; j++) {
                float4 cc = c_cent[j][i];        // uniform const load
                u64 c01 = pack2(cc.x, cc.y), c23 = pack2(cc.z, cc.w);
                fma2(dot[j], a01, c01); fma2(dot[j], a23, c23);
            }
        }

        float lo, hi;
        unpack2(zn, lo, hi);
        const float zz1 = 1.0f + (lo + hi);

        float q[K], rsum = 0.0f;
        #pragma unroll
        for (int j = 0; j < K; j++) {
            unpack2(dot[j], lo, hi);
            const float d = lo + hi;
            const float v = __fdividef(1.0f, fmaf(-2.0f, d, zz1 + s_cn[j]));
            q[j] = v; rsum += v;
        }
        const float inv = __fdividef(1.0f, rsum);

        const int row = tile * TILE_ROWS + tid;
        float* orow = qout + (size_t)row * K;
        #pragma unroll
        for (int j = 0; j < K; j++) { q[j] *= inv; csum[j] += q[j]; }
        #pragma unroll
        for (int m = 0; m < 5; m++) {
            float2 v; v.x = q[2 * m]; v.y = q[2 * m + 1];
            *(float2*)(orow + 2 * m) = v;
        }
        __syncthreads();    // protect s_z before next staging
    }

    // Block colsum partial -> g_part[blockIdx.x]
    #pragma unroll
    for (int j = 0; j < K; j++) {
        float v = csum[j];
        #pragma unroll
        for (int m = 16; m > 0; m >>= 1) v += __shfl_xor_sync(0xFFFFFFFFu, v, m);
        if (lane == 0) s_part[wrp][j] = v;
    }
    __syncthreads();
    if (tid < K)
        g_part[blockIdx.x][tid] =
            s_part[0][tid] + s_part[1][tid] + s_part[2][tid] + s_part[3][tid];

    // threadFenceReduction: last block finalizes colsums -> g_invf.
    __threadfence();
    __syncthreads();
    if (tid == 0) s_last = (atomicAdd(&g_ctr, 1) == NBLK1 - 1);
    __syncthreads();
    if (s_last) {
        __threadfence();
        float acc[K];
        #pragma unroll
        for (int j = 0; j < K; j++) acc[j] = 0.0f;
        for (int rr = tid; rr < NBLK1; rr += T1) {
            #pragma unroll
            for (int j = 0; j < K; j++) acc[j] += g_part[rr][j];
        }
        #pragma unroll
        for (int j = 0; j < K; j++) {
            float v = acc[j];
            #pragma unroll
            for (int m = 16; m > 0; m >>= 1) v += __shfl_xor_sync(0xFFFFFFFFu, v, m);
            if (lane == 0) s_part[wrp][j] = v;
        }
        __syncthreads();
        if (tid < K) {
            float s = 0.0f;
            #pragma unroll
            for (int w = 0; w < 4; w++) s += s_part[w][tid];
            g_invf[tid] = __fdividef(1.0f, s);
        }
        if (tid == 0) g_ctr = 0;   // reset for next replay
    }
}

// Kernel 2 (R5's measured-good version, bounds checks restored):
// p = rownorm( q^2 * g_invf ).
__global__ __launch_bounds__(T2) void k_p(
    const float* __restrict__ q,
    float* __restrict__ p)
{
    __shared__ float s_q[RPB2 * K];
    __shared__ float s_p[RPB2 * K];
    __shared__ float s_inv[K];

    const int tid = threadIdx.x;
    if (tid < K) s_inv[tid] = g_invf[tid];

    const float4* qg = (const float4*)(q + (size_t)blockIdx.x * RPB2 * K);
    #pragma unroll
    for (int i = 0; i < (RPB2 * K / 4 + T2 - 1) / T2; i++) {
        const int idx = i * T2 + tid;
        if (idx < RPB2 * K / 4) ((float4*)s_q)[idx] = qg[idx];
    }
    __syncthreads();

    float w[K], s = 0.0f;
    const float* qr = s_q + tid * K;
    #pragma unroll
    for (int j = 0; j < K; j++) {
        float v = qr[j];
        w[j] = v * v * s_inv[j];
        s += w[j];
    }
    const float inv = __fdividef(1.0f, s);
    float* pr = s_p + tid * K;
    #pragma unroll
    for (int j = 0; j < K; j++) pr[j] = w[j] * inv;
    __syncthreads();

    float4* pg = (float4*)(p + (size_t)blockIdx.x * RPB2 * K);
    #pragma unroll
    for (int i = 0; i < (RPB2 * K / 4 + T2 - 1) / T2; i++) {
        const int idx = i * T2 + tid;
        if (idx < RPB2 * K / 4) pg[idx] = ((const float4*)s_p)[idx];
    }
}

extern "C" void kernel_launch(void* const* d_in, const int* in_sizes, int n_in,
                              void* d_out, int out_size) {
    const float* z = (const float*)d_in[0];
    float* qout = (float*)d_out;
    float* pout = (float*)d_out + (size_t)BATCH * K;

    // Centers -> constant memory (D2D async copy: graph-capturable).
    cudaMemcpyToSymbolAsync(c_cent, d_in[1], K * DIM * sizeof(float), 0,
                            cudaMemcpyDeviceToDevice, 0);

    k_q<<<NBLK1, T1>>>(z, qout);
    k_p<<<NBLK2, T2>>>(qout, pout);
}

// round 8
// speedup vs baseline: 13.5688x; 1.0471x over previous
#include <cuda_runtime.h>

#define BATCH 262144
#define DIM   128
#define K     10

#define T1        128
#define TILE_ROWS 128
#define NTILES    (BATCH / TILE_ROWS)    // 2048
#define NBLK1     592                    // 148 SMs x 4 blocks
#define NCHUNK    4                      // 32 dims per chunk
#define CH_F4     8                      // float4 per row per chunk
#define BUF_F4    (TILE_ROWS * CH_F4)    // 1024 float4 = 16 KB

#define NBLK2 1024
#define T2    256
#define RPB2  (BATCH / NBLK2)            // 256

// Scratch (no allocs). g_part overwritten every launch; g_ctr returns to 0.
__device__ float g_part[NBLK1][K];
__device__ float g_invf[K];
__device__ int   g_ctr = 0;

typedef unsigned long long u64;

__device__ __forceinline__ u64 pack2(float lo, float hi) {
    u64 r; asm("mov.b64 %0, {%1, %2};" : "=l"(r) : "f"(lo), "f"(hi)); return r;
}
__device__ __forceinline__ void unpack2(u64 v, float& lo, float& hi) {
    asm("mov.b64 {%0, %1}, %2;" : "=f"(lo), "=f"(hi) : "l"(v));
}
__device__ __forceinline__ void fma2(u64& acc, u64 a, u64 b) {
    asm("fma.rn.f32x2 %0, %1, %2, %0;" : "+l"(acc) : "l"(a), "l"(b));
}
__device__ __forceinline__ void cp_async16(unsigned smem_addr, const void* g) {
    asm volatile("cp.async.cg.shared.global [%0], [%1], 16;"
                 :: "r"(smem_addr), "l"(g) : "memory");
}
__device__ __forceinline__ void cp_commit() {
    asm volatile("cp.async.commit_group;" ::: "memory");
}
__device__ __forceinline__ void cp_wait1() {
    asm volatile("cp.async.wait_group 1;" ::: "memory");
}
__device__ __forceinline__ void cp_wait0() {
    asm volatile("cp.async.wait_group 0;" ::: "memory");
}

// Kernel 1: q = rownorm( 1/(1 + ||z - mu||^2) ), colsums -> g_invf.
// Double-buffered cp.async pipeline over 16KB chunks (128 rows x 32 dims).
// Thread owns one row; centers are smem broadcast loads (N=1).
__global__ __launch_bounds__(T1) void k_q(
    const float* __restrict__ z,
    const float* __restrict__ c,
    float* __restrict__ qout)
{
    __shared__ float4 s_buf[2][BUF_F4];      // 2 x 16 KB
    __shared__ float4 s_c[K][DIM / 4];       // 5120 B
    __shared__ float  s_cn[K];
    __shared__ float  s_part[4][K];
    __shared__ int    s_last;

    const int tid  = threadIdx.x;
    const int lane = tid & 31;
    const int wrp  = tid >> 5;
    const int r7   = tid & 7;
    const unsigned sb0 = (unsigned)__cvta_generic_to_shared(&s_buf[0][0]);
    const unsigned sb1 = (unsigned)__cvta_generic_to_shared(&s_buf[1][0]);

    for (int i = tid; i < K * DIM / 4; i += T1)
        ((float4*)s_c)[i] = ((const float4*)c)[i];
    __syncthreads();
    if (tid < K) {
        float s = 0.0f;
        #pragma unroll
        for (int d = 0; d < DIM / 4; d++) {
            float4 v = s_c[tid][d];
            s = fmaf(v.x, v.x, fmaf(v.y, v.y, fmaf(v.z, v.z, fmaf(v.w, v.w, s))));
        }
        s_cn[tid] = s;
    }
    __syncthreads();

    float csum[K];
    #pragma unroll
    for (int j = 0; j < K; j++) csum[j] = 0.0f;

    // Stage chunk (t, k) into buffer base sb. Per k2-step a warp covers
    // 4 rows x 128B contiguous global. Swizzled dst for conflict-free LDS.
    auto stage = [&](unsigned sb, int t, int k) {
        const float4* zt = (const float4*)z + (size_t)t * TILE_ROWS * 32 + k * CH_F4;
        #pragma unroll
        for (int k2 = 0; k2 < CH_F4; k2++) {
            const int g   = k2 * T1 + tid;   // [0, 1024)
            const int row = g >> 3;
            const int i   = g & 7;
            cp_async16(sb + (unsigned)(row * CH_F4 + (i ^ (row & 7))) * 16,
                       zt + (size_t)row * 32 + i);
        }
        cp_commit();
    };

    int t   = blockIdx.x;
    int buf = 0;
    stage(sb0, t, 0);

    for (; t < NTILES; t += NBLK1) {
        u64 dot[K], zn = 0ull;
        #pragma unroll
        for (int j = 0; j < K; j++) dot[j] = 0ull;

        #pragma unroll
        for (int k = 0; k < NCHUNK; k++) {
            const int kn = (k + 1) & (NCHUNK - 1);
            const int tn = (k == NCHUNK - 1) ? t + NBLK1 : t;
            const bool have_next = (tn < NTILES);
            if (have_next) stage(buf ? sb0 : sb1, tn, kn);
            if (have_next) cp_wait1(); else cp_wait0();
            __syncthreads();

            const float4* b = s_buf[buf];
            #pragma unroll
            for (int i = 0; i < CH_F4; i++) {
                float4 a = b[tid * CH_F4 + (i ^ r7)];
                u64 a01 = pack2(a.x, a.y), a23 = pack2(a.z, a.w);
                fma2(zn, a01, a01); fma2(zn, a23, a23);
                #pragma unroll
                for (int j = 0; j < K; j++) {
                    float4 cc = s_c[j][k * CH_F4 + i];   // broadcast LDS
                    u64 c01 = pack2(cc.x, cc.y), c23 = pack2(cc.z, cc.w);
                    fma2(dot[j], a01, c01); fma2(dot[j], a23, c23);
                }
            }
            __syncthreads();    // readers done before this buf is re-staged
            buf ^= 1;
        }

        float lo, hi;
        unpack2(zn, lo, hi);
        const float zz1 = 1.0f + (lo + hi);

        float q[K], rsum = 0.0f;
        #pragma unroll
        for (int j = 0; j < K; j++) {
            unpack2(dot[j], lo, hi);
            const float d = lo + hi;
            const float v = __fdividef(1.0f, fmaf(-2.0f, d, zz1 + s_cn[j]));
            q[j] = v; rsum += v;
        }
        const float inv = __fdividef(1.0f, rsum);

        const int row = t * TILE_ROWS + tid;
        float* orow = qout + (size_t)row * K;
        #pragma unroll
        for (int j = 0; j < K; j++) { q[j] *= inv; csum[j] += q[j]; }
        #pragma unroll
        for (int m = 0; m < 5; m++) {
            float2 v; v.x = q[2 * m]; v.y = q[2 * m + 1];
            *(float2*)(orow + 2 * m) = v;
        }
    }

    // Block colsum partial -> g_part[blockIdx.x]
    #pragma unroll
    for (int j = 0; j < K; j++) {
        float v = csum[j];
        #pragma unroll
        for (int m = 16; m > 0; m >>= 1) v += __shfl_xor_sync(0xFFFFFFFFu, v, m);
        if (lane == 0) s_part[wrp][j] = v;
    }
    __syncthreads();
    if (tid < K)
        g_part[blockIdx.x][tid] =
            s_part[0][tid] + s_part[1][tid] + s_part[2][tid] + s_part[3][tid];

    // threadFenceReduction: last-arriving block finalizes colsums -> g_invf.
    __threadfence();
    __syncthreads();
    if (tid == 0) s_last = (atomicAdd(&g_ctr, 1) == NBLK1 - 1);
    __syncthreads();
    if (s_last) {
        __threadfence();
        float acc[K];
        #pragma unroll
        for (int j = 0; j < K; j++) acc[j] = 0.0f;
        for (int rr = tid; rr < NBLK1; rr += T1) {
            #pragma unroll
            for (int j = 0; j < K; j++) acc[j] += g_part[rr][j];
        }
        #pragma unroll
        for (int j = 0; j < K; j++) {
            float v = acc[j];
            #pragma unroll
            for (int m = 16; m > 0; m >>= 1) v += __shfl_xor_sync(0xFFFFFFFFu, v, m);
            if (lane == 0) s_part[wrp][j] = v;
        }
        __syncthreads();
        if (tid < K) {
            float s = 0.0f;
            #pragma unroll
            for (int w = 0; w < 4; w++) s += s_part[w][tid];
            g_invf[tid] = __fdividef(1.0f, s);
        }
        if (tid == 0) g_ctr = 0;   // reset for next replay
    }
}

// Kernel 2 (measured 7.2us): p = rownorm( q^2 * g_invf ).
__global__ __launch_bounds__(T2) void k_p(
    const float* __restrict__ q,
    float* __restrict__ p)
{
    __shared__ float s_q[RPB2 * K];
    __shared__ float s_p[RPB2 * K];
    __shared__ float s_inv[K];

    const int tid = threadIdx.x;
    if (tid < K) s_inv[tid] = g_invf[tid];

    const float4* qg = (const float4*)(q + (size_t)blockIdx.x * RPB2 * K);
    #pragma unroll
    for (int i = 0; i < (RPB2 * K / 4 + T2 - 1) / T2; i++) {
        const int idx = i * T2 + tid;
        if (idx < RPB2 * K / 4) ((float4*)s_q)[idx] = qg[idx];
    }
    __syncthreads();

    float w[K], s = 0.0f;
    const float* qr = s_q + tid * K;
    #pragma unroll
    for (int j = 0; j < K; j++) {
        float v = qr[j];
        w[j] = v * v * s_inv[j];
        s += w[j];
    }
    const float inv = __fdividef(1.0f, s);
    float* pr = s_p + tid * K;
    #pragma unroll
    for (int j = 0; j < K; j++) pr[j] = w[j] * inv;
    __syncthreads();

    float4* pg = (float4*)(p + (size_t)blockIdx.x * RPB2 * K);
    #pragma unroll
    for (int i = 0; i < (RPB2 * K / 4 + T2 - 1) / T2; i++) {
        const int idx = i * T2 + tid;
        if (idx < RPB2 * K / 4) pg[idx] = ((const float4*)s_p)[idx];
    }
}

extern "C" void kernel_launch(void* const* d_in, const int* in_sizes, int n_in,
                              void* d_out, int out_size) {
    const float* z = (const float*)d_in[0];
    const float* c = (const float*)d_in[1];
    float* qout = (float*)d_out;
    float* pout = (float*)d_out + (size_t)BATCH * K;

    k_q<<<NBLK1, T1>>>(z, c, qout);
    k_p<<<NBLK2, T2>>>(qout, pout);
}